// round 13
// baseline (speedup 1.0000x reference)
#include <cuda_runtime.h>
#include <cuda_fp16.h>

#define USER_NUM 50000
#define N_NODES  100000
#define EMB      64
#define ROWB     128    // bytes per fp16 row
#define ADJ_NNZ  1600000
#define S_NNZ    800000
#define TOT      (N_NODES * EMB)
#define BUF_ROWS 150000                     // [ego_users | h_users | ego_items]
#define BUFTOT   (BUF_ROWS * EMB)
#define SB 512
#define ADJ_NB ((N_NODES + SB - 1) / SB)    // 196
#define S_NB   ((USER_NUM + SB - 1) / SB)   // 98

// ---------------- scratch (device globals; zero-initialized at load) ----------------
__device__ __half g_bufA[BUFTOT];           // layer 0 state
__device__ __half g_bufB[BUFTOT];           // layer 1 state
__device__ __half g_bufC[BUFTOT];           // layer 2 state

__device__ int   g_adj_cnt[N_NODES];        // invariant: zero at kernel_launch entry
__device__ int   g_adj_ptr[N_NODES + 1];
__device__ int   g_adj_w[N_NODES];
__device__ uint2 g_adj_cv[ADJ_NNZ];         // (col*128, val bits)

__device__ int   g_s_cnt[USER_NUM];         // invariant: zero at kernel_launch entry
__device__ int   g_s_ptr[USER_NUM + 1];
__device__ int   g_s_w[USER_NUM];
__device__ uint2 g_s_cv[S_NNZ];             // (col*128, val bits)

__device__ int   g_bsumsA[SB];
__device__ int   g_bsumsB[SB];

// ego row index within a buffer: users at [0,50K), items at [100K,150K)
__device__ __forceinline__ int ego_row(int r) {
    return (r < USER_NUM) ? r : r + USER_NUM;
}

// ---------------- fused: hist(adj) + hist(s) + init(ego0 fp16 into bufA) ----------------
__global__ void hist_init_kernel(const int* __restrict__ adj_rows, const int* __restrict__ s_rows,
                                 int* __restrict__ adj_cnt, int* __restrict__ s_cnt,
                                 const float* __restrict__ ue, const float* __restrict__ ie,
                                 __half* __restrict__ buf) {
    int i = blockIdx.x * blockDim.x + threadIdx.x;
    if (i < ADJ_NNZ) {
        atomicAdd(adj_cnt + __ldcs(adj_rows + i), 1);
    } else if (i < ADJ_NNZ + S_NNZ) {
        atomicAdd(s_cnt + __ldcs(s_rows + (i - ADJ_NNZ)), 1);
    } else if (i < ADJ_NNZ + S_NNZ + TOT / 2) {
        int j = i - (ADJ_NNZ + S_NNZ);             // half2/float2 index over [users;items]
        const float2* src = (j < USER_NUM * EMB / 2) ? (const float2*)ue
                                                     : (const float2*)ie - USER_NUM * EMB / 2;
        float2 v = src[j];
        int dst = (j < USER_NUM * EMB / 2) ? j : j + USER_NUM * EMB / 2;  // item shift
        ((__half2*)buf)[dst] = __floats2half2_rn(v.x, v.y);
    }
}

// per-block exclusive scans of both count arrays
__global__ void scan1_kernel(const int* __restrict__ adj_cnt, int* __restrict__ adj_ptr,
                             const int* __restrict__ s_cnt, int* __restrict__ s_ptr,
                             int* __restrict__ bsumsA, int* __restrict__ bsumsB) {
    __shared__ int sh[SB];
    const int* cnt; int* ptr; int* bsums; int n; int b;
    if (blockIdx.x < ADJ_NB) { cnt = adj_cnt; ptr = adj_ptr; bsums = bsumsA; n = N_NODES; b = blockIdx.x; }
    else                     { cnt = s_cnt;   ptr = s_ptr;   bsums = bsumsB; n = USER_NUM; b = blockIdx.x - ADJ_NB; }
    int i = b * SB + threadIdx.x;
    int v = (i < n) ? cnt[i] : 0;
    sh[threadIdx.x] = v;
    __syncthreads();
    for (int off = 1; off < SB; off <<= 1) {
        int t = (threadIdx.x >= off) ? sh[threadIdx.x - off] : 0;
        __syncthreads();
        sh[threadIdx.x] += t;
        __syncthreads();
    }
    if (i < n) ptr[i] = sh[threadIdx.x] - v;
    if (threadIdx.x == SB - 1) bsums[b] = sh[SB - 1];
}

__global__ void scan2_kernel(int* __restrict__ bsumsA, int* __restrict__ bsumsB) {
    __shared__ int sh[SB];
    int* bs = (blockIdx.x == 0) ? bsumsA : bsumsB;
    int nb  = (blockIdx.x == 0) ? ADJ_NB : S_NB;
    int v = (threadIdx.x < nb) ? bs[threadIdx.x] : 0;
    sh[threadIdx.x] = v;
    __syncthreads();
    for (int off = 1; off < SB; off <<= 1) {
        int t = (threadIdx.x >= off) ? sh[threadIdx.x - off] : 0;
        __syncthreads();
        sh[threadIdx.x] += t;
        __syncthreads();
    }
    if (threadIdx.x < nb) bs[threadIdx.x] = sh[threadIdx.x] - v;
}

// add block offsets, seed working offsets, terminate rowptrs, re-zero cnt arrays
__global__ void scan3_kernel(int* __restrict__ adj_ptr, int* __restrict__ adj_w,
                             int* __restrict__ s_ptr, int* __restrict__ s_w,
                             const int* __restrict__ bsumsA, const int* __restrict__ bsumsB,
                             int* __restrict__ adj_cnt, int* __restrict__ s_cnt) {
    int i = blockIdx.x * blockDim.x + threadIdx.x;
    if (i < N_NODES) {
        int p = adj_ptr[i] + bsumsA[i / SB];
        adj_ptr[i] = p; adj_w[i] = p; adj_cnt[i] = 0;
        if (i == 0) adj_ptr[N_NODES] = ADJ_NNZ;
    } else if (i < N_NODES + USER_NUM) {
        int j = i - N_NODES;
        int p = s_ptr[j] + bsumsB[j / SB];
        s_ptr[j] = p; s_w[j] = p; s_cnt[j] = 0;
        if (j == 0) s_ptr[USER_NUM] = S_NNZ;
    }
}

// scatter both edge lists into packed (col*128, val) CSR payload
__global__ void scatter_kernel(const int* __restrict__ adj_rows, const int* __restrict__ adj_cols,
                               const float* __restrict__ adj_vals, int* __restrict__ adj_w,
                               uint2* __restrict__ adj_cv,
                               const int* __restrict__ s_rows, const int* __restrict__ s_cols,
                               const float* __restrict__ s_vals, int* __restrict__ s_w,
                               uint2* __restrict__ s_cv) {
    int i = blockIdx.x * blockDim.x + threadIdx.x;
    if (i < ADJ_NNZ) {
        int p = atomicAdd(adj_w + __ldcs(adj_rows + i), 1);
        adj_cv[p] = make_uint2((unsigned)__ldcs(adj_cols + i) * ROWB,
                               __float_as_uint(__ldcs(adj_vals + i)));
    } else if (i < ADJ_NNZ + S_NNZ) {
        int j = i - ADJ_NNZ;
        int p = atomicAdd(s_w + __ldcs(s_rows + j), 1);
        s_cv[p] = make_uint2((unsigned)__ldcs(s_cols + j) * ROWB,
                             __float_as_uint(__ldcs(s_vals + j)));
    }
}

// ---------------- edge-paired half-warp gather core ----------------
// Lanes 0-15 take even edges, lanes 16-31 odd edges of the SAME row.
// Each lane gathers 8 bytes (4 halves) at byte offset hb within the row.
// Caller must cross-add halves with shfl_xor(16) afterwards.
__device__ __forceinline__ float4 row_accum2(const uint2* __restrict__ cv, int e, int end,
                                             int half, int hb, const char* __restrict__ base,
                                             float4 a) {
    // main: 2 pair-iterations per loop = 4 edges, 2 gather LDG (4 lines in flight)
    for (; e + 3 < end; e += 4) {
        uint2 c0 = __ldg(cv + e + half);          // lanes<16: edge e   ; lanes>=16: e+1
        uint2 c1 = __ldg(cv + e + 2 + half);      // lanes<16: edge e+2 ; lanes>=16: e+3
        uint2 g0 = __ldg((const uint2*)(base + c0.x + hb));
        uint2 g1 = __ldg((const uint2*)(base + c1.x + hb));
        float w0 = __uint_as_float(c0.y), w1 = __uint_as_float(c1.y);
        float2 x0a = __half22float2(*(const __half2*)&g0.x);
        float2 x0b = __half22float2(*(const __half2*)&g0.y);
        float2 x1a = __half22float2(*(const __half2*)&g1.x);
        float2 x1b = __half22float2(*(const __half2*)&g1.y);
        a.x = fmaf(w0, x0a.x, fmaf(w1, x1a.x, a.x));
        a.y = fmaf(w0, x0a.y, fmaf(w1, x1a.y, a.y));
        a.z = fmaf(w0, x0b.x, fmaf(w1, x1b.x, a.z));
        a.w = fmaf(w0, x0b.y, fmaf(w1, x1b.y, a.w));
    }
    // tail: pairs with clamp (handles 1..3 leftover edges)
    for (; e < end; e += 2) {
        int ee = min(e + half, end - 1);
        uint2 c0 = __ldg(cv + ee);
        float w0 = (e + half < end) ? __uint_as_float(c0.y) : 0.f;
        uint2 g0 = __ldg((const uint2*)(base + c0.x + hb));
        float2 x0a = __half22float2(*(const __half2*)&g0.x);
        float2 x0b = __half22float2(*(const __half2*)&g0.y);
        a.x = fmaf(w0, x0a.x, a.x);
        a.y = fmaf(w0, x0a.y, a.y);
        a.z = fmaf(w0, x0b.x, a.z);
        a.w = fmaf(w0, x0b.y, a.w);
    }
    return a;
}

__device__ __forceinline__ float4 cross_half_add(float4 a) {
    a.x += __shfl_xor_sync(0xffffffffu, a.x, 16);
    a.y += __shfl_xor_sync(0xffffffffu, a.y, 16);
    a.z += __shfl_xor_sync(0xffffffffu, a.z, 16);
    a.w += __shfl_xor_sync(0xffffffffu, a.w, 16);
    return a;
}

__device__ __forceinline__ uint2 pack_half4(float4 a) {
    __half2 p0 = __floats2half2_rn(a.x, a.y);
    __half2 p1 = __floats2half2_rn(a.z, a.w);
    uint2 st;
    st.x = *(unsigned*)&p0;
    st.y = *(unsigned*)&p1;
    return st;
}

// users only: buf.h[u] = buf.ego[u] + sum val * buf.ego[col]
__global__ void s_spmm_kernel(const int* __restrict__ ptr, const uint2* __restrict__ cv,
                              __half* __restrict__ buf) {
    int row = blockIdx.x * (blockDim.x >> 5) + (threadIdx.x >> 5);
    int lane = threadIdx.x & 31;
    if (row >= USER_NUM) return;
    int half = lane >> 4;
    int hb = (lane & 15) * 8;
    int e0 = __ldg(ptr + row), end = __ldg(ptr + row + 1);
    float4 a = make_float4(0.f, 0.f, 0.f, 0.f);
    if (half == 0) {   // self term counted once
        uint2 s = *(const uint2*)((const char*)buf + (size_t)row * ROWB + hb);
        float2 sa = __half22float2(*(const __half2*)&s.x);
        float2 sb = __half22float2(*(const __half2*)&s.y);
        a = make_float4(sa.x, sa.y, sb.x, sb.y);
    }
    a = row_accum2(cv, e0, end, half, hb, (const char*)buf, a);
    a = cross_half_add(a);
    if (half == 0) {   // h region starts at row USER_NUM
        *(uint2*)((char*)buf + (size_t)(row + USER_NUM) * ROWB + hb) = pack_half4(a);
    }
}

// a = sum val * gbase[col], gbase = buf + 50K rows (col<50K -> h_users, col>=50K -> ego_items)
// last==0: nxt.ego[r] = half(a)
// last==1: out[r] = (input_row + ego1[r] + ego2[r] + a) * 0.25  (buf IS layer-2 state)
__global__ void adj_spmm_kernel(const int* __restrict__ ptr, const uint2* __restrict__ cv,
                                const __half* __restrict__ buf, __half* __restrict__ nxt,
                                const float* __restrict__ ue, const float* __restrict__ ie,
                                const __half* __restrict__ ego1,
                                float* __restrict__ out, int last) {
    int row = blockIdx.x * (blockDim.x >> 5) + (threadIdx.x >> 5);
    int lane = threadIdx.x & 31;
    if (row >= N_NODES) return;
    int half = lane >> 4;
    int hl = lane & 15;
    int hb = hl * 8;
    int e0 = __ldg(ptr + row), end = __ldg(ptr + row + 1);
    const char* gbase = (const char*)(buf + (size_t)USER_NUM * EMB);
    float4 a = row_accum2(cv, e0, end, half, hb, gbase, make_float4(0.f, 0.f, 0.f, 0.f));
    a = cross_half_add(a);
    if (half != 0) return;
    int er = ego_row(row);
    if (last) {
        const float4* in0 = (const float4*)((row < USER_NUM)
            ? (ue + (size_t)row * EMB) : (ie + (size_t)(row - USER_NUM) * EMB));
        float4 v0 = __ldg(in0 + hl);                                             // ego0 (exact)
        uint2 e1 = __ldg((const uint2*)((const char*)ego1 + (size_t)er * ROWB + hb));
        uint2 e2 = __ldg((const uint2*)((const char*)buf  + (size_t)er * ROWB + hb));
        float2 v1a = __half22float2(*(const __half2*)&e1.x);
        float2 v1b = __half22float2(*(const __half2*)&e1.y);
        float2 v2a = __half22float2(*(const __half2*)&e2.x);
        float2 v2b = __half22float2(*(const __half2*)&e2.y);
        float4 o;
        o.x = (v0.x + v1a.x + v2a.x + a.x) * 0.25f;
        o.y = (v0.y + v1a.y + v2a.y + a.y) * 0.25f;
        o.z = (v0.z + v1b.x + v2b.x + a.z) * 0.25f;
        o.w = (v0.w + v1b.y + v2b.y + a.w) * 0.25f;
        ((float4*)(out + (size_t)row * EMB))[hl] = o;
    } else {
        *(uint2*)((char*)nxt + (size_t)er * ROWB + hb) = pack_half4(a);
    }
}

extern "C" void kernel_launch(void* const* d_in, const int* in_sizes, int n_in,
                              void* d_out, int out_size) {
    const float* ue       = (const float*)d_in[0];
    const float* ie       = (const float*)d_in[1];
    const int*   adj_rows = (const int*)d_in[2];
    const int*   adj_cols = (const int*)d_in[3];
    const float* adj_vals = (const float*)d_in[4];
    const int*   s_rows   = (const int*)d_in[5];
    const int*   s_cols   = (const int*)d_in[6];
    const float* s_vals   = (const float*)d_in[7];

    __half *bufA, *bufB, *bufC;
    int *adj_cnt, *adj_ptr, *adj_w, *s_cnt, *s_ptr, *s_w, *bsumsA, *bsumsB;
    uint2 *adj_cv, *s_cv;
    cudaGetSymbolAddress((void**)&bufA,    g_bufA);
    cudaGetSymbolAddress((void**)&bufB,    g_bufB);
    cudaGetSymbolAddress((void**)&bufC,    g_bufC);
    cudaGetSymbolAddress((void**)&adj_cnt, g_adj_cnt);
    cudaGetSymbolAddress((void**)&adj_ptr, g_adj_ptr);
    cudaGetSymbolAddress((void**)&adj_w,   g_adj_w);
    cudaGetSymbolAddress((void**)&adj_cv,  g_adj_cv);
    cudaGetSymbolAddress((void**)&s_cnt,   g_s_cnt);
    cudaGetSymbolAddress((void**)&s_ptr,   g_s_ptr);
    cudaGetSymbolAddress((void**)&s_w,     g_s_w);
    cudaGetSymbolAddress((void**)&s_cv,    g_s_cv);
    cudaGetSymbolAddress((void**)&bsumsA,  g_bsumsA);
    cudaGetSymbolAddress((void**)&bsumsB,  g_bsumsB);

    const int TPB = 256;

    // ---- build CSR for both matrices + init ego0 (5 kernels) ----
    {
        int tot = ADJ_NNZ + S_NNZ + TOT / 2;
        hist_init_kernel<<<(tot + TPB - 1) / TPB, TPB>>>(adj_rows, s_rows, adj_cnt, s_cnt,
                                                         ue, ie, bufA);
    }
    scan1_kernel<<<ADJ_NB + S_NB, SB>>>(adj_cnt, adj_ptr, s_cnt, s_ptr, bsumsA, bsumsB);
    scan2_kernel<<<2, SB>>>(bsumsA, bsumsB);
    {
        int tot = N_NODES + USER_NUM;
        scan3_kernel<<<(tot + TPB - 1) / TPB, TPB>>>(adj_ptr, adj_w, s_ptr, s_w,
                                                     bsumsA, bsumsB, adj_cnt, s_cnt);
    }
    {
        int tot = ADJ_NNZ + S_NNZ;
        scatter_kernel<<<(tot + TPB - 1) / TPB, TPB>>>(adj_rows, adj_cols, adj_vals, adj_w, adj_cv,
                                                       s_rows, s_cols, s_vals, s_w, s_cv);
    }

    // ---- 3 layers (6 kernels) ----
    const int wpb = TPB / 32;
    const int s_blocks   = (USER_NUM + wpb - 1) / wpb;
    const int adj_blocks = (N_NODES + wpb - 1) / wpb;

    // layer 0: bufA -> bufB
    s_spmm_kernel<<<s_blocks, TPB>>>(s_ptr, s_cv, bufA);
    adj_spmm_kernel<<<adj_blocks, TPB>>>(adj_ptr, adj_cv, bufA, bufB,
                                         ue, ie, bufB, (float*)d_out, 0);
    // layer 1: bufB -> bufC
    s_spmm_kernel<<<s_blocks, TPB>>>(s_ptr, s_cv, bufB);
    adj_spmm_kernel<<<adj_blocks, TPB>>>(adj_ptr, adj_cv, bufB, bufC,
                                         ue, ie, bufB, (float*)d_out, 0);
    // layer 2: bufC -> fused final: out = (input + ego1(bufB) + ego2(bufC) + a) / 4
    s_spmm_kernel<<<s_blocks, TPB>>>(s_ptr, s_cv, bufC);
    adj_spmm_kernel<<<adj_blocks, TPB>>>(adj_ptr, adj_cv, bufC, /*nxt*/bufA,
                                         ue, ie, bufB, (float*)d_out, 1);
}

// round 14
// speedup vs baseline: 1.0694x; 1.0694x over previous
#include <cuda_runtime.h>
#include <cuda_fp16.h>

#define USER_NUM 50000
#define N_NODES  100000
#define EMB      64
#define ROWB     128    // bytes per fp16 row
#define ADJ_NNZ  1600000
#define S_NNZ    800000
#define TOT      (N_NODES * EMB)
#define SB 512
#define ADJ_NB ((N_NODES + SB - 1) / SB)    // 196
#define S_NB   ((USER_NUM + SB - 1) / SB)   // 98

// ---------------- scratch (device globals; zero-initialized at load) ----------------
__device__ __half g_egoA[TOT];              // ego0 (fp16 copy of inputs)
__device__ __half g_egoB[TOT];              // ego1
__device__ __half g_egoC[TOT];              // ego2
__device__ __half g_hFull[TOT];             // [u' ; v] gather source for ADJ

__device__ int   g_adj_cnt[N_NODES];        // invariant: zero at kernel_launch entry
__device__ int   g_adj_ptr[N_NODES + 1];
__device__ int   g_adj_w[N_NODES];
__device__ uint2 g_adj_cv[ADJ_NNZ];         // (col*128, val bits)

__device__ int   g_s_cnt[USER_NUM];         // invariant: zero at kernel_launch entry
__device__ int   g_s_ptr[USER_NUM + 1];
__device__ int   g_s_w[USER_NUM];
__device__ uint2 g_s_cv[S_NNZ];             // (col*128, val bits)

__device__ int   g_bsumsA[SB];              // raw per-block sums (not pre-scanned)
__device__ int   g_bsumsB[SB];

// ---------------- fused: hist(adj) + hist(s) + init(ego0 fp16) ----------------
__global__ void hist_init_kernel(const int* __restrict__ adj_rows, const int* __restrict__ s_rows,
                                 int* __restrict__ adj_cnt, int* __restrict__ s_cnt,
                                 const float* __restrict__ ue, const float* __restrict__ ie,
                                 __half* __restrict__ ego) {
    int i = blockIdx.x * blockDim.x + threadIdx.x;
    if (i < ADJ_NNZ) {
        atomicAdd(adj_cnt + __ldcs(adj_rows + i), 1);
    } else if (i < ADJ_NNZ + S_NNZ) {
        atomicAdd(s_cnt + __ldcs(s_rows + (i - ADJ_NNZ)), 1);
    } else if (i < ADJ_NNZ + S_NNZ + TOT / 2) {
        int j = i - (ADJ_NNZ + S_NNZ);             // half2/float2 index
        const float2* src = (j < USER_NUM * EMB / 2) ? (const float2*)ue
                                                     : (const float2*)ie - USER_NUM * EMB / 2;
        float2 v = src[j];
        ((__half2*)ego)[j] = __floats2half2_rn(v.x, v.y);
    }
}

// per-block exclusive scans of both count arrays; raw block sums out
__global__ void scan1_kernel(const int* __restrict__ adj_cnt, int* __restrict__ adj_ptr,
                             const int* __restrict__ s_cnt, int* __restrict__ s_ptr,
                             int* __restrict__ bsumsA, int* __restrict__ bsumsB) {
    __shared__ int sh[SB];
    const int* cnt; int* ptr; int* bsums; int n; int b;
    if (blockIdx.x < ADJ_NB) { cnt = adj_cnt; ptr = adj_ptr; bsums = bsumsA; n = N_NODES; b = blockIdx.x; }
    else                     { cnt = s_cnt;   ptr = s_ptr;   bsums = bsumsB; n = USER_NUM; b = blockIdx.x - ADJ_NB; }
    int i = b * SB + threadIdx.x;
    int v = (i < n) ? cnt[i] : 0;
    sh[threadIdx.x] = v;
    __syncthreads();
    for (int off = 1; off < SB; off <<= 1) {
        int t = (threadIdx.x >= off) ? sh[threadIdx.x - off] : 0;
        __syncthreads();
        sh[threadIdx.x] += t;
        __syncthreads();
    }
    if (i < n) ptr[i] = sh[threadIdx.x] - v;
    if (threadIdx.x == SB - 1) bsums[b] = sh[SB - 1];
}

// fused scan2+scan3: each block re-derives the block-sum prefixes in smem,
// then adds offsets, seeds working ptrs, terminates rowptrs, re-zeroes cnt arrays.
__global__ void scan3_kernel(int* __restrict__ adj_ptr, int* __restrict__ adj_w,
                             int* __restrict__ s_ptr, int* __restrict__ s_w,
                             const int* __restrict__ bsumsA, const int* __restrict__ bsumsB,
                             int* __restrict__ adj_cnt, int* __restrict__ s_cnt) {
    __shared__ int shA[256];   // exclusive prefix of bsumsA (ADJ_NB=196 <= 256)
    __shared__ int shB[128];   // exclusive prefix of bsumsB (S_NB=98 <= 128)
    int t = threadIdx.x;
    if (t < 256) shA[t] = (t < ADJ_NB) ? bsumsA[t] : 0;
    if (t < 128) shB[t] = (t < S_NB)   ? bsumsB[t] : 0;
    __syncthreads();
    int vA = (t < 256) ? shA[t] : 0;
    int vB = (t < 128) ? shB[t] : 0;
    for (int off = 1; off < 256; off <<= 1) {
        int ta = (t < 256 && t >= off) ? shA[t - off] : 0;
        int tb = (t < 128 && t >= off && off < 128) ? shB[t - off] : 0;
        __syncthreads();
        if (t < 256) shA[t] += ta;
        if (t < 128 && off < 128) shB[t] += tb;
        __syncthreads();
    }
    // convert inclusive -> exclusive
    if (t < 256) shA[t] -= vA;
    if (t < 128) shB[t] -= vB;
    __syncthreads();

    int i = blockIdx.x * blockDim.x + t;
    if (i < N_NODES) {
        int p = adj_ptr[i] + shA[i / SB];
        adj_ptr[i] = p; adj_w[i] = p; adj_cnt[i] = 0;
        if (i == 0) adj_ptr[N_NODES] = ADJ_NNZ;
    } else if (i < N_NODES + USER_NUM) {
        int j = i - N_NODES;
        int p = s_ptr[j] + shB[j / SB];
        s_ptr[j] = p; s_w[j] = p; s_cnt[j] = 0;
        if (j == 0) s_ptr[USER_NUM] = S_NNZ;
    }
}

// scatter both edge lists into packed (col*128, val) CSR payload
__global__ void scatter_kernel(const int* __restrict__ adj_rows, const int* __restrict__ adj_cols,
                               const float* __restrict__ adj_vals, int* __restrict__ adj_w,
                               uint2* __restrict__ adj_cv,
                               const int* __restrict__ s_rows, const int* __restrict__ s_cols,
                               const float* __restrict__ s_vals, int* __restrict__ s_w,
                               uint2* __restrict__ s_cv) {
    int i = blockIdx.x * blockDim.x + threadIdx.x;
    if (i < ADJ_NNZ) {
        int p = atomicAdd(adj_w + __ldcs(adj_rows + i), 1);
        adj_cv[p] = make_uint2((unsigned)__ldcs(adj_cols + i) * ROWB,
                               __float_as_uint(__ldcs(adj_vals + i)));
    } else if (i < ADJ_NNZ + S_NNZ) {
        int j = i - ADJ_NNZ;
        int p = atomicAdd(s_w + __ldcs(s_rows + j), 1);
        s_cv[p] = make_uint2((unsigned)__ldcs(s_cols + j) * ROWB,
                             __float_as_uint(__ldcs(s_vals + j)));
    }
}

// ---------------- warp-per-row gather core (single base, byte-offset cols, MLP-4) ----------------
__device__ __forceinline__ float2 row_accum(const uint2* __restrict__ cv, int e, int end,
                                            int lane, const char* __restrict__ base, float2 a) {
    const int lb = lane * 4;   // byte offset of this lane's half2 within a row
    for (; e + 3 < end; e += 4) {
        uint2 c0 = __ldg(cv + e),     c1 = __ldg(cv + e + 1);
        uint2 c2 = __ldg(cv + e + 2), c3 = __ldg(cv + e + 3);
        float2 x0 = __half22float2(__ldg((const __half2*)(base + c0.x + lb)));
        float2 x1 = __half22float2(__ldg((const __half2*)(base + c1.x + lb)));
        float2 x2 = __half22float2(__ldg((const __half2*)(base + c2.x + lb)));
        float2 x3 = __half22float2(__ldg((const __half2*)(base + c3.x + lb)));
        float w0 = __uint_as_float(c0.y), w1 = __uint_as_float(c1.y);
        float w2 = __uint_as_float(c2.y), w3 = __uint_as_float(c3.y);
        a.x = fmaf(w0, x0.x, fmaf(w1, x1.x, fmaf(w2, x2.x, fmaf(w3, x3.x, a.x))));
        a.y = fmaf(w0, x0.y, fmaf(w1, x1.y, fmaf(w2, x2.y, fmaf(w3, x3.y, a.y))));
    }
    for (; e < end; e++) {
        uint2 c0 = __ldg(cv + e);
        float w0 = __uint_as_float(c0.y);
        float2 x0 = __half22float2(__ldg((const __half2*)(base + c0.x + lb)));
        a.x = fmaf(w0, x0.x, a.x);
        a.y = fmaf(w0, x0.y, a.y);
    }
    return a;
}

// rows < USER_NUM: hFull[r] = ego[r] + sum val*ego[col]
// rows >= USER_NUM: hFull[r] = ego[r]   (item passthrough copy)
__global__ void s_spmm_kernel(const int* __restrict__ ptr, const uint2* __restrict__ cv,
                              const __half* __restrict__ ego, __half* __restrict__ hFull) {
    int row = blockIdx.x * (blockDim.x >> 5) + (threadIdx.x >> 5);
    int lane = threadIdx.x & 31;
    if (row >= N_NODES) return;
    __half2 self = ((const __half2*)(ego + (size_t)row * EMB))[lane];
    if (row < USER_NUM) {
        int e0 = __ldg(ptr + row), end = __ldg(ptr + row + 1);
        float2 a = __half22float2(self);
        a = row_accum(cv, e0, end, lane, (const char*)ego, a);
        ((__half2*)(hFull + (size_t)row * EMB))[lane] = __floats2half2_rn(a.x, a.y);
    } else {
        ((__half2*)(hFull + (size_t)row * EMB))[lane] = self;
    }
}

// a = sum val * hFull[col]
// last==0: nxt[r] = half(a)
// last==1: out[r] = (input_row + ego1[r] + ego2[r] + a) * 0.25  (ego param IS ego2 on last)
__global__ void adj_spmm_kernel(const int* __restrict__ ptr, const uint2* __restrict__ cv,
                                const __half* __restrict__ hFull, const __half* __restrict__ ego,
                                __half* __restrict__ nxt,
                                const float* __restrict__ ue, const float* __restrict__ ie,
                                const __half* __restrict__ ego1,
                                float* __restrict__ out, int last) {
    int row = blockIdx.x * (blockDim.x >> 5) + (threadIdx.x >> 5);
    int lane = threadIdx.x & 31;
    if (row >= N_NODES) return;
    int e0 = __ldg(ptr + row), end = __ldg(ptr + row + 1);
    float2 a = row_accum(cv, e0, end, lane, (const char*)hFull, make_float2(0.f, 0.f));
    if (last) {
        const float2* in0 = (row < USER_NUM)
            ? (const float2*)ue + (size_t)row * (EMB / 2)
            : (const float2*)ie + (size_t)(row - USER_NUM) * (EMB / 2);
        float2 v0 = __ldg(in0 + lane);                                            // ego0 (exact)
        float2 v1 = __half22float2(__ldg((const __half2*)(ego1 + (size_t)row * EMB) + lane));
        float2 v2 = __half22float2(__ldg((const __half2*)(ego  + (size_t)row * EMB) + lane));
        ((float2*)(out + (size_t)row * EMB))[lane] =
            make_float2((v0.x + v1.x + v2.x + a.x) * 0.25f,
                        (v0.y + v1.y + v2.y + a.y) * 0.25f);
    } else {
        ((__half2*)(nxt + (size_t)row * EMB))[lane] = __floats2half2_rn(a.x, a.y);
    }
}

extern "C" void kernel_launch(void* const* d_in, const int* in_sizes, int n_in,
                              void* d_out, int out_size) {
    const float* ue       = (const float*)d_in[0];
    const float* ie       = (const float*)d_in[1];
    const int*   adj_rows = (const int*)d_in[2];
    const int*   adj_cols = (const int*)d_in[3];
    const float* adj_vals = (const float*)d_in[4];
    const int*   s_rows   = (const int*)d_in[5];
    const int*   s_cols   = (const int*)d_in[6];
    const float* s_vals   = (const float*)d_in[7];

    __half *egoA, *egoB, *egoC, *hFull;
    int *adj_cnt, *adj_ptr, *adj_w, *s_cnt, *s_ptr, *s_w, *bsumsA, *bsumsB;
    uint2 *adj_cv, *s_cv;
    cudaGetSymbolAddress((void**)&egoA,    g_egoA);
    cudaGetSymbolAddress((void**)&egoB,    g_egoB);
    cudaGetSymbolAddress((void**)&egoC,    g_egoC);
    cudaGetSymbolAddress((void**)&hFull,   g_hFull);
    cudaGetSymbolAddress((void**)&adj_cnt, g_adj_cnt);
    cudaGetSymbolAddress((void**)&adj_ptr, g_adj_ptr);
    cudaGetSymbolAddress((void**)&adj_w,   g_adj_w);
    cudaGetSymbolAddress((void**)&adj_cv,  g_adj_cv);
    cudaGetSymbolAddress((void**)&s_cnt,   g_s_cnt);
    cudaGetSymbolAddress((void**)&s_ptr,   g_s_ptr);
    cudaGetSymbolAddress((void**)&s_w,     g_s_w);
    cudaGetSymbolAddress((void**)&s_cv,    g_s_cv);
    cudaGetSymbolAddress((void**)&bsumsA,  g_bsumsA);
    cudaGetSymbolAddress((void**)&bsumsB,  g_bsumsB);

    const int TPB = 256;

    // ---- build CSR for both matrices + init ego0 (4 kernels) ----
    {
        int tot = ADJ_NNZ + S_NNZ + TOT / 2;
        hist_init_kernel<<<(tot + TPB - 1) / TPB, TPB>>>(adj_rows, s_rows, adj_cnt, s_cnt,
                                                         ue, ie, egoA);
    }
    scan1_kernel<<<ADJ_NB + S_NB, SB>>>(adj_cnt, adj_ptr, s_cnt, s_ptr, bsumsA, bsumsB);
    {
        int tot = N_NODES + USER_NUM;
        scan3_kernel<<<(tot + TPB - 1) / TPB, TPB>>>(adj_ptr, adj_w, s_ptr, s_w,
                                                     bsumsA, bsumsB, adj_cnt, s_cnt);
    }
    {
        int tot = ADJ_NNZ + S_NNZ;
        scatter_kernel<<<(tot + TPB - 1) / TPB, TPB>>>(adj_rows, adj_cols, adj_vals, adj_w, adj_cv,
                                                       s_rows, s_cols, s_vals, s_w, s_cv);
    }

    // ---- 3 layers (6 kernels); ego0=egoA, ego1=egoB, ego2=egoC ----
    const int wpb = TPB / 32;
    const int all_blocks = (N_NODES + wpb - 1) / wpb;

    // layer 0: read egoA -> write egoB
    s_spmm_kernel<<<all_blocks, TPB>>>(s_ptr, s_cv, egoA, hFull);
    adj_spmm_kernel<<<all_blocks, TPB>>>(adj_ptr, adj_cv, hFull, egoA, egoB,
                                         ue, ie, egoB, (float*)d_out, 0);
    // layer 1: read egoB -> write egoC
    s_spmm_kernel<<<all_blocks, TPB>>>(s_ptr, s_cv, egoB, hFull);
    adj_spmm_kernel<<<all_blocks, TPB>>>(adj_ptr, adj_cv, hFull, egoB, egoC,
                                         ue, ie, egoB, (float*)d_out, 0);
    // layer 2: read egoC -> fused final: out = (input + egoB + egoC + a) / 4
    s_spmm_kernel<<<all_blocks, TPB>>>(s_ptr, s_cv, egoC, hFull);
    adj_spmm_kernel<<<all_blocks, TPB>>>(adj_ptr, adj_cv, hFull, egoC, /*nxt*/egoA,
                                         ue, ie, egoB, (float*)d_out, 1);
}

// round 15
// speedup vs baseline: 1.0768x; 1.0069x over previous
#include <cuda_runtime.h>
#include <cuda_fp16.h>

#define USER_NUM 50000
#define N_NODES  100000
#define EMB      64
#define ROWB     128    // bytes per fp16 row
#define ADJ_NNZ  1600000
#define S_NNZ    800000
#define TOT      (N_NODES * EMB)
#define SB 512
#define ADJ_NB ((N_NODES + SB - 1) / SB)    // 196
#define S_NB   ((USER_NUM + SB - 1) / SB)   // 98

// ---------------- scratch (device globals; zero-initialized at load) ----------------
__device__ __half g_egoA[TOT];              // ego0 (fp16 copy of inputs)
__device__ __half g_egoB[TOT];              // ego1
__device__ __half g_egoC[TOT];              // ego2
__device__ __half g_hFull[TOT];             // [u' ; v] gather source for ADJ

__device__ int   g_adj_cnt[N_NODES];        // invariant: zero at kernel_launch entry
__device__ int   g_adj_ptr[N_NODES + 1];
__device__ int   g_adj_rank[ADJ_NNZ];       // per-edge within-row rank (from hist)
__device__ uint2 g_adj_cv[ADJ_NNZ];         // (col*128, val bits)

__device__ int   g_s_cnt[USER_NUM];         // invariant: zero at kernel_launch entry
__device__ int   g_s_ptr[USER_NUM + 1];
__device__ int   g_s_rank[S_NNZ];
__device__ uint2 g_s_cv[S_NNZ];             // (col*128, val bits)

__device__ int   g_bsumsA[SB];              // raw per-block sums (not pre-scanned)
__device__ int   g_bsumsB[SB];

// ---------------- fused: hist(adj) + hist(s) + rank record + init(ego0 fp16) ----------------
__global__ void hist_init_kernel(const int* __restrict__ adj_rows, const int* __restrict__ s_rows,
                                 int* __restrict__ adj_cnt, int* __restrict__ s_cnt,
                                 int* __restrict__ adj_rank, int* __restrict__ s_rank,
                                 const float* __restrict__ ue, const float* __restrict__ ie,
                                 __half* __restrict__ ego) {
    int i = blockIdx.x * blockDim.x + threadIdx.x;
    if (i < ADJ_NNZ) {
        adj_rank[i] = atomicAdd(adj_cnt + __ldcs(adj_rows + i), 1);
    } else if (i < ADJ_NNZ + S_NNZ) {
        int j = i - ADJ_NNZ;
        s_rank[j] = atomicAdd(s_cnt + __ldcs(s_rows + j), 1);
    } else if (i < ADJ_NNZ + S_NNZ + TOT / 2) {
        int j = i - (ADJ_NNZ + S_NNZ);             // half2/float2 index
        const float2* src = (j < USER_NUM * EMB / 2) ? (const float2*)ue
                                                     : (const float2*)ie - USER_NUM * EMB / 2;
        float2 v = src[j];
        ((__half2*)ego)[j] = __floats2half2_rn(v.x, v.y);
    }
}

// per-block exclusive scans of both count arrays; raw block sums out
__global__ void scan1_kernel(const int* __restrict__ adj_cnt, int* __restrict__ adj_ptr,
                             const int* __restrict__ s_cnt, int* __restrict__ s_ptr,
                             int* __restrict__ bsumsA, int* __restrict__ bsumsB) {
    __shared__ int sh[SB];
    const int* cnt; int* ptr; int* bsums; int n; int b;
    if (blockIdx.x < ADJ_NB) { cnt = adj_cnt; ptr = adj_ptr; bsums = bsumsA; n = N_NODES; b = blockIdx.x; }
    else                     { cnt = s_cnt;   ptr = s_ptr;   bsums = bsumsB; n = USER_NUM; b = blockIdx.x - ADJ_NB; }
    int i = b * SB + threadIdx.x;
    int v = (i < n) ? cnt[i] : 0;
    sh[threadIdx.x] = v;
    __syncthreads();
    for (int off = 1; off < SB; off <<= 1) {
        int t = (threadIdx.x >= off) ? sh[threadIdx.x - off] : 0;
        __syncthreads();
        sh[threadIdx.x] += t;
        __syncthreads();
    }
    if (i < n) ptr[i] = sh[threadIdx.x] - v;
    if (threadIdx.x == SB - 1) bsums[b] = sh[SB - 1];
}

// fused scan2+scan3: each block re-derives the block-sum prefixes in smem,
// then adds offsets, terminates rowptrs, re-zeroes cnt arrays.
__global__ void scan3_kernel(int* __restrict__ adj_ptr, int* __restrict__ s_ptr,
                             const int* __restrict__ bsumsA, const int* __restrict__ bsumsB,
                             int* __restrict__ adj_cnt, int* __restrict__ s_cnt) {
    __shared__ int shA[256];   // exclusive prefix of bsumsA (ADJ_NB=196 <= 256)
    __shared__ int shB[128];   // exclusive prefix of bsumsB (S_NB=98 <= 128)
    int t = threadIdx.x;
    if (t < 256) shA[t] = (t < ADJ_NB) ? bsumsA[t] : 0;
    if (t < 128) shB[t] = (t < S_NB)   ? bsumsB[t] : 0;
    __syncthreads();
    int vA = (t < 256) ? shA[t] : 0;
    int vB = (t < 128) ? shB[t] : 0;
    for (int off = 1; off < 256; off <<= 1) {
        int ta = (t < 256 && t >= off) ? shA[t - off] : 0;
        int tb = (t < 128 && t >= off && off < 128) ? shB[t - off] : 0;
        __syncthreads();
        if (t < 256) shA[t] += ta;
        if (t < 128 && off < 128) shB[t] += tb;
        __syncthreads();
    }
    if (t < 256) shA[t] -= vA;   // inclusive -> exclusive
    if (t < 128) shB[t] -= vB;
    __syncthreads();

    int i = blockIdx.x * blockDim.x + t;
    if (i < N_NODES) {
        int p = adj_ptr[i] + shA[i / SB];
        adj_ptr[i] = p; adj_cnt[i] = 0;
        if (i == 0) adj_ptr[N_NODES] = ADJ_NNZ;
    } else if (i < N_NODES + USER_NUM) {
        int j = i - N_NODES;
        int p = s_ptr[j] + shB[j / SB];
        s_ptr[j] = p; s_cnt[j] = 0;
        if (j == 0) s_ptr[USER_NUM] = S_NNZ;
    }
}

// atomic-free scatter: p = ptr[row] + rank[i]
__global__ void scatter_kernel(const int* __restrict__ adj_rows, const int* __restrict__ adj_cols,
                               const float* __restrict__ adj_vals, const int* __restrict__ adj_rank,
                               const int* __restrict__ adj_ptr, uint2* __restrict__ adj_cv,
                               const int* __restrict__ s_rows, const int* __restrict__ s_cols,
                               const float* __restrict__ s_vals, const int* __restrict__ s_rank,
                               const int* __restrict__ s_ptr, uint2* __restrict__ s_cv) {
    int i = blockIdx.x * blockDim.x + threadIdx.x;
    if (i < ADJ_NNZ) {
        int p = __ldg(adj_ptr + __ldcs(adj_rows + i)) + __ldcs(adj_rank + i);
        adj_cv[p] = make_uint2((unsigned)__ldcs(adj_cols + i) * ROWB,
                               __float_as_uint(__ldcs(adj_vals + i)));
    } else if (i < ADJ_NNZ + S_NNZ) {
        int j = i - ADJ_NNZ;
        int p = __ldg(s_ptr + __ldcs(s_rows + j)) + __ldcs(s_rank + j);
        s_cv[p] = make_uint2((unsigned)__ldcs(s_cols + j) * ROWB,
                             __float_as_uint(__ldcs(s_vals + j)));
    }
}

// ---------------- warp-per-row gather core (single base, byte-offset cols, MLP-4) ----------------
__device__ __forceinline__ float2 row_accum(const uint2* __restrict__ cv, int e, int end,
                                            int lane, const char* __restrict__ base, float2 a) {
    const int lb = lane * 4;   // byte offset of this lane's half2 within a row
    for (; e + 3 < end; e += 4) {
        uint2 c0 = __ldg(cv + e),     c1 = __ldg(cv + e + 1);
        uint2 c2 = __ldg(cv + e + 2), c3 = __ldg(cv + e + 3);
        float2 x0 = __half22float2(__ldg((const __half2*)(base + c0.x + lb)));
        float2 x1 = __half22float2(__ldg((const __half2*)(base + c1.x + lb)));
        float2 x2 = __half22float2(__ldg((const __half2*)(base + c2.x + lb)));
        float2 x3 = __half22float2(__ldg((const __half2*)(base + c3.x + lb)));
        float w0 = __uint_as_float(c0.y), w1 = __uint_as_float(c1.y);
        float w2 = __uint_as_float(c2.y), w3 = __uint_as_float(c3.y);
        a.x = fmaf(w0, x0.x, fmaf(w1, x1.x, fmaf(w2, x2.x, fmaf(w3, x3.x, a.x))));
        a.y = fmaf(w0, x0.y, fmaf(w1, x1.y, fmaf(w2, x2.y, fmaf(w3, x3.y, a.y))));
    }
    for (; e < end; e++) {
        uint2 c0 = __ldg(cv + e);
        float w0 = __uint_as_float(c0.y);
        float2 x0 = __half22float2(__ldg((const __half2*)(base + c0.x + lb)));
        a.x = fmaf(w0, x0.x, a.x);
        a.y = fmaf(w0, x0.y, a.y);
    }
    return a;
}

// rows < USER_NUM: hFull[r] = ego[r] + sum val*ego[col]
// rows >= USER_NUM: hFull[r] = ego[r]   (item passthrough copy)
__global__ void s_spmm_kernel(const int* __restrict__ ptr, const uint2* __restrict__ cv,
                              const __half* __restrict__ ego, __half* __restrict__ hFull) {
    int row = blockIdx.x * (blockDim.x >> 5) + (threadIdx.x >> 5);
    int lane = threadIdx.x & 31;
    if (row >= N_NODES) return;
    __half2 self = ((const __half2*)(ego + (size_t)row * EMB))[lane];
    if (row < USER_NUM) {
        int e0 = __ldg(ptr + row), end = __ldg(ptr + row + 1);
        float2 a = __half22float2(self);
        a = row_accum(cv, e0, end, lane, (const char*)ego, a);
        ((__half2*)(hFull + (size_t)row * EMB))[lane] = __floats2half2_rn(a.x, a.y);
    } else {
        ((__half2*)(hFull + (size_t)row * EMB))[lane] = self;
    }
}

// a = sum val * hFull[col]
// last==0: nxt[r] = half(a)
// last==1: out[r] = (input_row + ego1[r] + ego2[r] + a) * 0.25  (ego param IS ego2 on last)
__global__ void adj_spmm_kernel(const int* __restrict__ ptr, const uint2* __restrict__ cv,
                                const __half* __restrict__ hFull, const __half* __restrict__ ego,
                                __half* __restrict__ nxt,
                                const float* __restrict__ ue, const float* __restrict__ ie,
                                const __half* __restrict__ ego1,
                                float* __restrict__ out, int last) {
    int row = blockIdx.x * (blockDim.x >> 5) + (threadIdx.x >> 5);
    int lane = threadIdx.x & 31;
    if (row >= N_NODES) return;
    int e0 = __ldg(ptr + row), end = __ldg(ptr + row + 1);
    float2 a = row_accum(cv, e0, end, lane, (const char*)hFull, make_float2(0.f, 0.f));
    if (last) {
        const float2* in0 = (row < USER_NUM)
            ? (const float2*)ue + (size_t)row * (EMB / 2)
            : (const float2*)ie + (size_t)(row - USER_NUM) * (EMB / 2);
        float2 v0 = __ldg(in0 + lane);                                            // ego0 (exact)
        float2 v1 = __half22float2(__ldg((const __half2*)(ego1 + (size_t)row * EMB) + lane));
        float2 v2 = __half22float2(__ldg((const __half2*)(ego  + (size_t)row * EMB) + lane));
        ((float2*)(out + (size_t)row * EMB))[lane] =
            make_float2((v0.x + v1.x + v2.x + a.x) * 0.25f,
                        (v0.y + v1.y + v2.y + a.y) * 0.25f);
    } else {
        ((__half2*)(nxt + (size_t)row * EMB))[lane] = __floats2half2_rn(a.x, a.y);
    }
}

extern "C" void kernel_launch(void* const* d_in, const int* in_sizes, int n_in,
                              void* d_out, int out_size) {
    const float* ue       = (const float*)d_in[0];
    const float* ie       = (const float*)d_in[1];
    const int*   adj_rows = (const int*)d_in[2];
    const int*   adj_cols = (const int*)d_in[3];
    const float* adj_vals = (const float*)d_in[4];
    const int*   s_rows   = (const int*)d_in[5];
    const int*   s_cols   = (const int*)d_in[6];
    const float* s_vals   = (const float*)d_in[7];

    __half *egoA, *egoB, *egoC, *hFull;
    int *adj_cnt, *adj_ptr, *adj_rank, *s_cnt, *s_ptr, *s_rank, *bsumsA, *bsumsB;
    uint2 *adj_cv, *s_cv;
    cudaGetSymbolAddress((void**)&egoA,     g_egoA);
    cudaGetSymbolAddress((void**)&egoB,     g_egoB);
    cudaGetSymbolAddress((void**)&egoC,     g_egoC);
    cudaGetSymbolAddress((void**)&hFull,    g_hFull);
    cudaGetSymbolAddress((void**)&adj_cnt,  g_adj_cnt);
    cudaGetSymbolAddress((void**)&adj_ptr,  g_adj_ptr);
    cudaGetSymbolAddress((void**)&adj_rank, g_adj_rank);
    cudaGetSymbolAddress((void**)&adj_cv,   g_adj_cv);
    cudaGetSymbolAddress((void**)&s_cnt,    g_s_cnt);
    cudaGetSymbolAddress((void**)&s_ptr,    g_s_ptr);
    cudaGetSymbolAddress((void**)&s_rank,   g_s_rank);
    cudaGetSymbolAddress((void**)&s_cv,     g_s_cv);
    cudaGetSymbolAddress((void**)&bsumsA,   g_bsumsA);
    cudaGetSymbolAddress((void**)&bsumsB,   g_bsumsB);

    const int TPB = 256;

    // ---- build CSR for both matrices + init ego0 (4 kernels) ----
    {
        int tot = ADJ_NNZ + S_NNZ + TOT / 2;
        hist_init_kernel<<<(tot + TPB - 1) / TPB, TPB>>>(adj_rows, s_rows, adj_cnt, s_cnt,
                                                         adj_rank, s_rank, ue, ie, egoA);
    }
    scan1_kernel<<<ADJ_NB + S_NB, SB>>>(adj_cnt, adj_ptr, s_cnt, s_ptr, bsumsA, bsumsB);
    {
        int tot = N_NODES + USER_NUM;
        scan3_kernel<<<(tot + TPB - 1) / TPB, TPB>>>(adj_ptr, s_ptr,
                                                     bsumsA, bsumsB, adj_cnt, s_cnt);
    }
    {
        int tot = ADJ_NNZ + S_NNZ;
        scatter_kernel<<<(tot + TPB - 1) / TPB, TPB>>>(adj_rows, adj_cols, adj_vals, adj_rank,
                                                       adj_ptr, adj_cv,
                                                       s_rows, s_cols, s_vals, s_rank,
                                                       s_ptr, s_cv);
    }

    // ---- 3 layers (6 kernels); ego0=egoA, ego1=egoB, ego2=egoC ----
    const int wpb = TPB / 32;
    const int all_blocks = (N_NODES + wpb - 1) / wpb;

    // layer 0: read egoA -> write egoB
    s_spmm_kernel<<<all_blocks, TPB>>>(s_ptr, s_cv, egoA, hFull);
    adj_spmm_kernel<<<all_blocks, TPB>>>(adj_ptr, adj_cv, hFull, egoA, egoB,
                                         ue, ie, egoB, (float*)d_out, 0);
    // layer 1: read egoB -> write egoC
    s_spmm_kernel<<<all_blocks, TPB>>>(s_ptr, s_cv, egoB, hFull);
    adj_spmm_kernel<<<all_blocks, TPB>>>(adj_ptr, adj_cv, hFull, egoB, egoC,
                                         ue, ie, egoB, (float*)d_out, 0);
    // layer 2: read egoC -> fused final: out = (input + egoB + egoC + a) / 4
    s_spmm_kernel<<<all_blocks, TPB>>>(s_ptr, s_cv, egoC, hFull);
    adj_spmm_kernel<<<all_blocks, TPB>>>(adj_ptr, adj_cv, hFull, egoC, /*nxt*/egoA,
                                         ue, ie, egoB, (float*)d_out, 1);
}